// round 10
// baseline (speedup 1.0000x reference)
#include <cuda_runtime.h>
#include <cuda_bf16.h>
#include <cstdint>
#include <math.h>

#define An 32
#define Bn 128
#define Nn 4096
#define Tt 5
#define Hh 4
#define DHh 64
#define Dd 256
#define Ll 64
#define FIN1 24
#define NROWS 20480          // 640 blocks * 32 rows

typedef unsigned long long ull;

// ---------------- scratch ----------------
__device__ unsigned short g_x2h[NROWS * Dd];    // bf16 hi of x2 (row-major)
__device__ unsigned short g_x2l[NROWS * Dd];    // bf16 lo (residual)
__device__ unsigned short g_w2th[Dd * Dd];      // W2^T hi  [n][k]
__device__ unsigned short g_w2tl[Dd * Dd];      // W2^T lo
__device__ float g_ego[Tt * Bn * Dd];
__device__ float g_k[Tt * Bn * Dd];
__device__ float g_v[Tt * Bn * Dd];
__device__ float g_q[Bn * Dd];

// ---------------- f32x2 helpers ----------------
__device__ __forceinline__ ull pack2(float lo, float hi) {
    ull r; asm("mov.b64 %0, {%1, %2};" : "=l"(r) : "f"(lo), "f"(hi)); return r;
}
__device__ __forceinline__ ull dup2(float v) { return pack2(v, v); }
__device__ __forceinline__ void fma2(ull& acc, ull a, ull b) {
    asm("fma.rn.f32x2 %0, %1, %2, %0;" : "+l"(acc) : "l"(a), "l"(b));
}
__device__ __forceinline__ float2 unpack2(ull v) {
    float2 f; asm("mov.b64 {%0, %1}, %2;" : "=f"(f.x), "=f"(f.y) : "l"(v)); return f;
}

// ---------------- warp mma helper ----------------
__device__ __forceinline__ void mma16816(float* d,
    uint32_t a0, uint32_t a1, uint32_t a2, uint32_t a3,
    uint32_t b0, uint32_t b1)
{
    asm volatile("mma.sync.aligned.m16n8k16.row.col.f32.bf16.bf16.f32 "
        "{%0,%1,%2,%3}, {%4,%5,%6,%7}, {%8,%9}, {%0,%1,%2,%3};"
        : "+f"(d[0]), "+f"(d[1]), "+f"(d[2]), "+f"(d[3])
        : "r"(a0), "r"(a1), "r"(a2), "r"(a3), "r"(b0), "r"(b1));
}

// ---------------------------------------------------------------------------
// GAT layer 1 per (t, block): GEMM1 + logits + softmax + agg -> x2 (bf16 hi/lo)
// ---------------------------------------------------------------------------
#define G1_H 6912
#define G1_ALS 15232
#define G1_ALD 15360
#define G1_TOT 15488
#define HSTRIDE 260

__global__ __launch_bounds__(256, 3)
void gat1_kernel(const float* __restrict__ node_feats,
                 const float* __restrict__ W1,
                 const float* __restrict__ a1s, const float* __restrict__ a1d,
                 const float* __restrict__ b1)
{
    extern __shared__ float sm[];
    float* x1_sm  = sm;
    float* W1_sm  = sm + 32 * FIN1;
    float* alpha1 = sm;                 // alias (x1/W1 dead)
    float* h_sm   = sm + G1_H;
    float* als    = sm + G1_ALS;
    float* ald    = sm + G1_ALD;

    const int tid = threadIdx.x;
    const int t   = blockIdx.x / Bn;
    const int bb  = blockIdx.x % Bn;

    {
        const float* xblk = node_feats + ((size_t)t * Nn + (size_t)bb * An) * FIN1;
        for (int i = tid; i < 32 * FIN1; i += 256) x1_sm[i] = xblk[i];
        const float4* Wsrc = reinterpret_cast<const float4*>(W1);
        float4* Wdst = reinterpret_cast<float4*>(W1_sm);
        #pragma unroll
        for (int i = 0; i < (FIN1 * Dd) / 4; i += 256) Wdst[i + tid] = Wsrc[i + tid];
    }
    __syncthreads();

    const int cp = tid & 63;
    const int r0 = (tid >> 6) * 8;

    // GEMM1 (R5-proven 8x2 tiling)
    {
        ull acc0[8], acc1[8];
        #pragma unroll
        for (int i = 0; i < 8; i++) { acc0[i] = 0ull; acc1[i] = 0ull; }
        #pragma unroll
        for (int k = 0; k < FIN1; k += 2) {
            float2 xv[8];
            #pragma unroll
            for (int i = 0; i < 8; i++)
                xv[i] = *reinterpret_cast<const float2*>(&x1_sm[(r0 + i) * FIN1 + k]);
            {
                const ull* Wr = reinterpret_cast<const ull*>(&W1_sm[k * Dd]);
                ull w0 = Wr[cp], w1 = Wr[cp + 64];
                #pragma unroll
                for (int i = 0; i < 8; i++) { ull d = dup2(xv[i].x); fma2(acc0[i], d, w0); fma2(acc1[i], d, w1); }
            }
            {
                const ull* Wr = reinterpret_cast<const ull*>(&W1_sm[(k + 1) * Dd]);
                ull w0 = Wr[cp], w1 = Wr[cp + 64];
                #pragma unroll
                for (int i = 0; i < 8; i++) { ull d = dup2(xv[i].y); fma2(acc0[i], d, w0); fma2(acc1[i], d, w1); }
            }
        }
        ull* h64 = reinterpret_cast<ull*>(h_sm);
        #pragma unroll
        for (int i = 0; i < 8; i++) {
            h64[(r0 + i) * (HSTRIDE / 2) + cp]      = acc0[i];
            h64[(r0 + i) * (HSTRIDE / 2) + cp + 64] = acc1[i];
        }
    }
    __syncthreads();

    // logits1
    if (tid < 128) {
        const int r = tid & 31, head = tid >> 5;
        const float* hrow = &h_sm[r * HSTRIDE + head * DHh];
        const float* as = &a1s[head * DHh];
        const float* ad = &a1d[head * DHh];
        float s1 = 0.f, s2 = 0.f;
        #pragma unroll 8
        for (int j = 0; j < DHh; j++) { float hv = hrow[j]; s1 = fmaf(hv, as[j], s1); s2 = fmaf(hv, ad[j], s2); }
        als[head * 32 + r] = s1;
        ald[head * 32 + r] = s2;
    }
    __syncthreads();

    // softmax1
    if (tid < 128) {
        const int d = tid & 31, head = tid >> 5;
        float* arow = &alpha1[head * (32 * 33) + d * 33];
        const float adv = ald[head * 32 + d];
        float m = -1e30f;
        #pragma unroll
        for (int s = 0; s < 32; s++) {
            float e = als[head * 32 + s] + adv;
            e = (e >= 0.f) ? e : 0.2f * e;
            arow[s] = e; m = fmaxf(m, e);
        }
        float z = 0.f;
        #pragma unroll
        for (int s = 0; s < 32; s++) { float p = expf(arow[s] - m); arow[s] = p; z += p; }
        const float inv = 1.f / (z + 1e-16f);
        #pragma unroll
        for (int s = 0; s < 32; s++) arow[s] *= inv;
    }
    __syncthreads();

    // aggregation1 -> global bf16 hi/lo
    {
        const int head = tid >> 6;
        const int lane = tid & 63;
        const int cpl  = lane & 15;
        const int d0   = (lane >> 4) * 8;
        const ull* h64 = reinterpret_cast<const ull*>(h_sm);
        const float* arow = &alpha1[head * (32 * 33)];

        ull acc0[8], acc1[8];
        #pragma unroll
        for (int i = 0; i < 8; i++) { acc0[i] = 0ull; acc1[i] = 0ull; }
        #pragma unroll 4
        for (int s = 0; s < 32; s++) {
            ull hv0 = h64[s * (HSTRIDE / 2) + head * 32 + cpl];
            ull hv1 = h64[s * (HSTRIDE / 2) + head * 32 + cpl + 16];
            #pragma unroll
            for (int dd = 0; dd < 8; dd++) {
                ull a = dup2(arow[(d0 + dd) * 33 + s]);
                fma2(acc0[dd], a, hv0); fma2(acc1[dd], a, hv1);
            }
        }
        const int c0 = head * 64 + 2 * cpl;
        const int c1 = c0 + 32;
        float2 bv0 = *reinterpret_cast<const float2*>(&b1[c0]);
        float2 bv1 = *reinterpret_cast<const float2*>(&b1[c1]);
        #pragma unroll
        for (int dd = 0; dd < 8; dd++) {
            float2 o0 = unpack2(acc0[dd]);
            float2 o1 = unpack2(acc1[dd]);
            o0.x = fmaxf(o0.x + bv0.x, 0.f); o0.y = fmaxf(o0.y + bv0.y, 0.f);
            o1.x = fmaxf(o1.x + bv1.x, 0.f); o1.y = fmaxf(o1.y + bv1.y, 0.f);
            const size_t grow = (size_t)blockIdx.x * 32 + d0 + dd;
            {
                __nv_bfloat162 hv = __floats2bfloat162_rn(o0.x, o0.y);
                __nv_bfloat162 lv = __floats2bfloat162_rn(o0.x - __low2float(hv), o0.y - __high2float(hv));
                *reinterpret_cast<__nv_bfloat162*>(&g_x2h[grow * Dd + c0]) = hv;
                *reinterpret_cast<__nv_bfloat162*>(&g_x2l[grow * Dd + c0]) = lv;
            }
            {
                __nv_bfloat162 hv = __floats2bfloat162_rn(o1.x, o1.y);
                __nv_bfloat162 lv = __floats2bfloat162_rn(o1.x - __low2float(hv), o1.y - __high2float(hv));
                *reinterpret_cast<__nv_bfloat162*>(&g_x2h[grow * Dd + c1]) = hv;
                *reinterpret_cast<__nv_bfloat162*>(&g_x2l[grow * Dd + c1]) = lv;
            }
        }
    }
}

// ---------------------------------------------------------------------------
// W2 transpose + bf16 hi/lo split. grid 256 (n), 256 threads (k).
// ---------------------------------------------------------------------------
__global__ __launch_bounds__(256)
void prep_w2_kernel(const float* __restrict__ W2)
{
    const int n = blockIdx.x;
    const int k = threadIdx.x;
    float w = W2[(size_t)k * Dd + n];
    __nv_bfloat16 h = __float2bfloat16(w);
    __nv_bfloat16 l = __float2bfloat16(w - __bfloat162float(h));
    reinterpret_cast<__nv_bfloat16*>(g_w2th)[(size_t)n * Dd + k] = h;
    reinterpret_cast<__nv_bfloat16*>(g_w2tl)[(size_t)n * Dd + k] = l;
}

// ---------------------------------------------------------------------------
// GEMM2 (mma.sync, 3xBF16) FUSED with GAT-2 tail.
// 160 CTAs x 512 threads. Tile 128x256 (full N) = 4 graph blocks per CTA.
// Epilogue: acc -> smem tile -> logits2 -> softmax(d=0) -> agg2 -> g_ego.
// smem: staging Ah/Al[128][72] + Bh/Bl[256][72] = 110592 B, then reused as
//       tile[128][266] f32 (136192) + als/ald (4096) + alpha (2112) = 142400 B.
// ---------------------------------------------------------------------------
#define GP 72
#define TS 266
#define EP_ALS (128 * TS * 4)
#define EP_ALD (EP_ALS + 2048)
#define EP_ALPHA (EP_ALD + 2048)
#define G2_SMEM (EP_ALPHA + 2112)

__global__ __launch_bounds__(512, 1)
void gemm2_fused_kernel(const float* __restrict__ a2s, const float* __restrict__ a2d,
                        const float* __restrict__ b2)
{
    extern __shared__ char smraw[];
    unsigned short* sAh = reinterpret_cast<unsigned short*>(smraw);
    unsigned short* sAl = sAh + 128 * GP;
    unsigned short* sBh = sAh + 2 * 128 * GP;
    unsigned short* sBl = sBh + 256 * GP;
    float* tile  = reinterpret_cast<float*>(smraw);
    float* als   = reinterpret_cast<float*>(smraw + EP_ALS);    // [4][128]
    float* ald   = reinterpret_cast<float*>(smraw + EP_ALD);
    float* alpha = reinterpret_cast<float*>(smraw + EP_ALPHA);  // [16][33]

    const int tid  = threadIdx.x;
    const int wid  = tid >> 5;
    const int lane = tid & 31;
    const int nhalf = wid >> 3;          // 0/1 -> col half
    const int wr    = wid & 7;           // row group
    const int row0  = blockIdx.x * 128;
    const int n0    = nhalf * 128;
    const int g     = lane >> 2;         // 0..7
    const int cq    = (lane & 3) * 2;    // 0,2,4,6

    float acc[16][4];
    #pragma unroll
    for (int j = 0; j < 16; j++)
        #pragma unroll
        for (int i = 0; i < 4; i++) acc[j][i] = 0.f;

    for (int kc = 0; kc < Dd; kc += 64) {
        __syncthreads();
        // stage A (128 rows) hi/lo
        #pragma unroll
        for (int q = tid; q < 2048; q += 512) {
            int r  = q >> 4;
            int k4 = (q & 15) * 4;
            size_t ga = (size_t)(row0 + r) * Dd + kc + k4;
            *reinterpret_cast<ull*>(&sAh[r * GP + k4]) = *reinterpret_cast<const ull*>(&g_x2h[ga]);
            *reinterpret_cast<ull*>(&sAl[r * GP + k4]) = *reinterpret_cast<const ull*>(&g_x2l[ga]);
        }
        // stage B (256 rows) hi/lo
        #pragma unroll
        for (int q = tid; q < 4096; q += 512) {
            int r  = q >> 4;
            int k4 = (q & 15) * 4;
            size_t gb = (size_t)r * Dd + kc + k4;
            *reinterpret_cast<ull*>(&sBh[r * GP + k4]) = *reinterpret_cast<const ull*>(&g_w2th[gb]);
            *reinterpret_cast<ull*>(&sBl[r * GP + k4]) = *reinterpret_cast<const ull*>(&g_w2tl[gb]);
        }
        __syncthreads();

        #pragma unroll
        for (int s = 0; s < 4; s++) {
            const int kb = s * 16 + cq;
            const int ra = wr * 16 + g;
            uint32_t ah0 = *reinterpret_cast<const uint32_t*>(&sAh[ra * GP + kb]);
            uint32_t ah1 = *reinterpret_cast<const uint32_t*>(&sAh[(ra + 8) * GP + kb]);
            uint32_t ah2 = *reinterpret_cast<const uint32_t*>(&sAh[ra * GP + kb + 8]);
            uint32_t ah3 = *reinterpret_cast<const uint32_t*>(&sAh[(ra + 8) * GP + kb + 8]);
            uint32_t al0 = *reinterpret_cast<const uint32_t*>(&sAl[ra * GP + kb]);
            uint32_t al1 = *reinterpret_cast<const uint32_t*>(&sAl[(ra + 8) * GP + kb]);
            uint32_t al2 = *reinterpret_cast<const uint32_t*>(&sAl[ra * GP + kb + 8]);
            uint32_t al3 = *reinterpret_cast<const uint32_t*>(&sAl[(ra + 8) * GP + kb + 8]);

            #pragma unroll
            for (int j = 0; j < 16; j++) {
                const int nb = n0 + j * 8 + g;
                uint32_t bh0 = *reinterpret_cast<const uint32_t*>(&sBh[nb * GP + kb]);
                uint32_t bh1 = *reinterpret_cast<const uint32_t*>(&sBh[nb * GP + kb + 8]);
                uint32_t bl0 = *reinterpret_cast<const uint32_t*>(&sBl[nb * GP + kb]);
                uint32_t bl1 = *reinterpret_cast<const uint32_t*>(&sBl[nb * GP + kb + 8]);
                mma16816(acc[j], ah0, ah1, ah2, ah3, bh0, bh1);   // hi*hi
                mma16816(acc[j], ah0, ah1, ah2, ah3, bl0, bl1);   // hi*lo
                mma16816(acc[j], al0, al1, al2, al3, bh0, bh1);   // lo*hi
            }
        }
    }
    __syncthreads();   // staging dead; reuse smem as epilogue tile

    // write accumulators to smem tile (float2, TS even)
    {
        const int row = wr * 16 + g;
        #pragma unroll
        for (int j = 0; j < 16; j++) {
            const int col = n0 + j * 8 + cq;
            *reinterpret_cast<float2*>(&tile[row * TS + col])       = make_float2(acc[j][0], acc[j][1]);
            *reinterpret_cast<float2*>(&tile[(row + 8) * TS + col]) = make_float2(acc[j][2], acc[j][3]);
        }
    }
    __syncthreads();

    // logits2: 512 threads = (head 0..3) x (row 0..127)
    {
        const int head = tid >> 7;
        const int r = tid & 127;
        const float* hrow = &tile[r * TS + head * DHh];
        const float* as = &a2s[head * DHh];
        const float* ad = &a2d[head * DHh];
        float s1 = 0.f, s2 = 0.f;
        #pragma unroll 8
        for (int j = 0; j < DHh; j++) { float hv = hrow[j]; s1 = fmaf(hv, as[j], s1); s2 = fmaf(hv, ad[j], s2); }
        als[head * 128 + r] = s1;
        ald[head * 128 + r] = s2;
    }
    __syncthreads();

    // softmax2 (d=0) per (block 0..3, head 0..3)
    if (tid < 16) {
        const int blk = tid >> 2;
        const int head = tid & 3;
        const float adv = ald[head * 128 + blk * 32];
        float* arow = &alpha[(blk * 4 + head) * 33];
        const float* asrc = &als[head * 128 + blk * 32];
        float m = -1e30f;
        #pragma unroll
        for (int s = 0; s < 32; s++) {
            float e = asrc[s] + adv;
            e = (e >= 0.f) ? e : 0.2f * e;
            arow[s] = e; m = fmaxf(m, e);
        }
        float z = 0.f;
        #pragma unroll
        for (int s = 0; s < 32; s++) { float p = expf(arow[s] - m); arow[s] = p; z += p; }
        const float inv = 1.f / (z + 1e-16f);
        #pragma unroll
        for (int s = 0; s < 32; s++) arow[s] *= inv;
    }
    __syncthreads();

    // aggregation2 (d=0): 1024 outputs over 512 threads (2 each)
    #pragma unroll
    for (int it = tid; it < 1024; it += 512) {
        const int blk = it >> 8;
        const int c = it & 255;
        const int head = c >> 6;
        const float* arow = &alpha[(blk * 4 + head) * 33];
        const float* hcol = &tile[blk * 32 * TS + c];
        float a = 0.f;
        #pragma unroll 8
        for (int s = 0; s < 32; s++)
            a = fmaf(arow[s], hcol[s * TS], a);
        a = fmaxf(a + b2[c], 0.f);
        g_ego[(size_t)(blockIdx.x * 4 + blk) * Dd + c] = a;
    }
}

// ---------------------------------------------------------------------------
// QKV GEMM, smem-staged weights (proven). 176 CTAs.
// ---------------------------------------------------------------------------
__global__ __launch_bounds__(256)
void qkv_kernel(const float* __restrict__ wq, const float* __restrict__ bq,
                const float* __restrict__ wk, const float* __restrict__ bk,
                const float* __restrict__ wv, const float* __restrict__ bv)
{
    __shared__ float x_sm[16 * Dd];
    __shared__ float w_sm[64 * 128];

    const int id  = blockIdx.x;
    const int tile = id >> 1;
    const int ch   = id & 1;
    const int tid  = threadIdx.x;

    const float* W; const float* bias; float* outbase; int row0; int xrow0;
    if (tile < 40)      { W = wk; bias = bk; row0 = tile * 16;        outbase = g_k; xrow0 = row0; }
    else if (tile < 80) { W = wv; bias = bv; row0 = (tile - 40) * 16; outbase = g_v; xrow0 = row0; }
    else                { W = wq; bias = bq; row0 = (tile - 80) * 16; outbase = g_q; xrow0 = 512 + row0; }

    {
        const float4* s4 = reinterpret_cast<const float4*>(g_ego + (size_t)xrow0 * Dd);
        float4* d4 = reinterpret_cast<float4*>(x_sm);
        #pragma unroll
        for (int i = 0; i < (16 * Dd) / 4; i += 256) d4[i + tid] = s4[i + tid];
    }

    const int cp = tid & 63;
    const int r0 = (tid >> 6) * 4;

    ull acc[4];
    #pragma unroll
    for (int i = 0; i < 4; i++) acc[i] = 0ull;

    #pragma unroll 1
    for (int c4 = 0; c4 < 4; c4++) {
        __syncthreads();
        {
            float4* wd = reinterpret_cast<float4*>(w_sm);
            #pragma unroll
            for (int i = tid; i < 2048; i += 256) {
                int r  = i >> 5;
                int c4i = i & 31;
                wd[i] = *reinterpret_cast<const float4*>(&W[(size_t)(c4 * 64 + r) * Dd + ch * 128 + c4i * 4]);
            }
        }
        __syncthreads();

        const ull* wu = reinterpret_cast<const ull*>(w_sm);
        #pragma unroll 4
        for (int k = 0; k < 64; k += 2) {
            float2 xv[4];
            #pragma unroll
            for (int r = 0; r < 4; r++)
                xv[r] = *reinterpret_cast<const float2*>(&x_sm[(r0 + r) * Dd + c4 * 64 + k]);
            ull w0 = wu[k * 64 + cp];
            ull w1 = wu[(k + 1) * 64 + cp];
            #pragma unroll
            for (int r = 0; r < 4; r++) { ull d = dup2(xv[r].x); fma2(acc[r], d, w0); }
            #pragma unroll
            for (int r = 0; r < 4; r++) { ull d = dup2(xv[r].y); fma2(acc[r], d, w1); }
        }
    }

    const int c = ch * 128 + 2 * cp;
    float2 bv2 = *reinterpret_cast<const float2*>(&bias[c]);
    #pragma unroll
    for (int r = 0; r < 4; r++) {
        float2 o = unpack2(acc[r]);
        o.x += bv2.x; o.y += bv2.y;
        *reinterpret_cast<float2*>(&outbase[(size_t)(row0 + r0 + r) * Dd + c]) = o;
    }
}

// ---------------------------------------------------------------------------
// attn + wo + output heads, fused. 16-wide batched weight loads (proven).
// ---------------------------------------------------------------------------
__global__ __launch_bounds__(256)
void post_kernel(const float* __restrict__ wo, const float* __restrict__ bo,
                 const float* __restrict__ lm_w, const float* __restrict__ lm_b,
                 const float* __restrict__ lv_w, const float* __restrict__ lv_b,
                 const float* __restrict__ ap_w, const float* __restrict__ ap_b,
                 const float* __restrict__ bh_w, const float* __restrict__ bh_b,
                 float* __restrict__ out)
{
    __shared__ float ksm[Tt][Dd];
    __shared__ float vsm[Tt][Dd];
    __shared__ float qsm[Dd];
    __shared__ float attn[Hh][Tt];
    __shared__ float ctx[Dd];
    __shared__ float feat[Dd];
    __shared__ float musm[Ll];

    const int b = blockIdx.x;
    const int tid = threadIdx.x;
    const int c = tid;

    #pragma unroll
    for (int t = 0; t < Tt; t++) {
        ksm[t][c] = g_k[((size_t)t * Bn + b) * Dd + c];
        vsm[t][c] = g_v[((size_t)t * Bn + b) * Dd + c];
    }
    qsm[c] = g_q[(size_t)b * Dd + c];
    __syncthreads();

    if (tid < Hh * Tt) {
        const int head = tid / Tt;
        const int t = tid % Tt;
        float s = 0.f;
        #pragma unroll 8
        for (int j = 0; j < DHh; j++)
            s = fmaf(qsm[head * DHh + j], ksm[t][head * DHh + j], s);
        attn[head][t] = s * 0.125f;
    }
    __syncthreads();

    if (tid < Hh) {
        float m = -1e30f;
        #pragma unroll
        for (int t = 0; t < Tt; t++) m = fmaxf(m, attn[tid][t]);
        float z = 0.f;
        #pragma unroll
        for (int t = 0; t < Tt; t++) { float p = expf(attn[tid][t] - m); attn[tid][t] = p; z += p; }
        float inv = 1.f / z;
        #pragma unroll
        for (int t = 0; t < Tt; t++) attn[tid][t] *= inv;
    }
    __syncthreads();

    {
        const int head = c >> 6;
        float a = 0.f;
        #pragma unroll
        for (int t = 0; t < Tt; t++) a = fmaf(attn[head][t], vsm[t][c], a);
        ctx[c] = a;
    }
    __syncthreads();

    {
        float f = bo[c];
        #pragma unroll 1
        for (int k = 0; k < Dd; k += 16) {
            float w[16];
            #pragma unroll
            for (int j = 0; j < 16; j++) w[j] = __ldg(&wo[(size_t)(k + j) * Dd + c]);
            #pragma unroll
            for (int j = 0; j < 16; j++) f = fmaf(ctx[k + j], w[j], f);
        }
        feat[c] = f;
    }
    __syncthreads();

    float* ob = out + (size_t)b * 400;

    if (tid < 64) {
        float m = lm_b[tid];
        #pragma unroll 1
        for (int k = 0; k < Dd; k += 16) {
            float w[16];
            #pragma unroll
            for (int j = 0; j < 16; j++) w[j] = __ldg(&lm_w[(size_t)(k + j) * Ll + tid]);
            #pragma unroll
            for (int j = 0; j < 16; j++) m = fmaf(feat[k + j], w[j], m);
        }
        musm[tid] = m;
        ob[tid] = m;
    } else if (tid < 128) {
        const int cc = tid - 64;
        float m = lv_b[cc];
        #pragma unroll 1
        for (int k = 0; k < Dd; k += 16) {
            float w[16];
            #pragma unroll
            for (int j = 0; j < 16; j++) w[j] = __ldg(&lv_w[(size_t)(k + j) * Ll + cc]);
            #pragma unroll
            for (int j = 0; j < 16; j++) m = fmaf(feat[k + j], w[j], m);
        }
        ob[64 + cc] = m;
    } else if (tid < 144) {
        const int cc = tid - 128;
        float m = bh_b[cc];
        #pragma unroll 1
        for (int k = 0; k < Dd; k += 16) {
            float w[16];
            #pragma unroll
            for (int j = 0; j < 16; j++) w[j] = __ldg(&bh_w[(size_t)(k + j) * 16 + cc]);
            #pragma unroll
            for (int j = 0; j < 16; j++) m = fmaf(feat[k + j], w[j], m);
        }
        ob[384 + cc] = m;
    }
    __syncthreads();

    {
        float a = ap_b[c];
        #pragma unroll 1
        for (int k = 0; k < Ll; k += 16) {
            float w[16];
            #pragma unroll
            for (int j = 0; j < 16; j++) w[j] = __ldg(&ap_w[(size_t)(k + j) * Dd + c]);
            #pragma unroll
            for (int j = 0; j < 16; j++) a = fmaf(musm[k + j], w[j], a);
        }
        ob[128 + c] = a;
    }
}

// ---------------------------------------------------------------------------
extern "C" void kernel_launch(void* const* d_in, const int* in_sizes, int n_in,
                              void* d_out, int out_size)
{
    const float* node_feats = (const float*)d_in[0];
    const float* gat1_w  = (const float*)d_in[2];
    const float* gat1_as = (const float*)d_in[3];
    const float* gat1_ad = (const float*)d_in[4];
    const float* gat1_b  = (const float*)d_in[5];
    const float* gat2_w  = (const float*)d_in[6];
    const float* gat2_as = (const float*)d_in[7];
    const float* gat2_ad = (const float*)d_in[8];
    const float* gat2_b  = (const float*)d_in[9];
    const float* wq = (const float*)d_in[10];
    const float* bq = (const float*)d_in[11];
    const float* wk = (const float*)d_in[12];
    const float* bk = (const float*)d_in[13];
    const float* wv = (const float*)d_in[14];
    const float* bv = (const float*)d_in[15];
    const float* wo = (const float*)d_in[16];
    const float* bo = (const float*)d_in[17];
    const float* lm_w = (const float*)d_in[18];
    const float* lm_b = (const float*)d_in[19];
    const float* lv_w = (const float*)d_in[20];
    const float* lv_b = (const float*)d_in[21];
    const float* ap_w = (const float*)d_in[22];
    const float* ap_b = (const float*)d_in[23];
    const float* bh_w = (const float*)d_in[24];
    const float* bh_b = (const float*)d_in[25];
    float* out = (float*)d_out;

    const size_t sm1 = (size_t)G1_TOT * sizeof(float);
    cudaFuncSetAttribute(gat1_kernel, cudaFuncAttributeMaxDynamicSharedMemorySize, (int)sm1);
    cudaFuncSetAttribute(gemm2_fused_kernel, cudaFuncAttributeMaxDynamicSharedMemorySize, G2_SMEM);

    prep_w2_kernel<<<256, 256>>>(gat2_w);
    gat1_kernel<<<Tt * Bn, 256, sm1>>>(node_feats, gat1_w, gat1_as, gat1_ad, gat1_b);
    gemm2_fused_kernel<<<NROWS / 128, 512, G2_SMEM>>>(gat2_as, gat2_ad, gat2_b);
    qkv_kernel<<<176, 256>>>(wq, bq, wk, bk, wv, bv);
    post_kernel<<<Bn, 256>>>(wo, bo, lm_w, lm_b, lv_w, lv_b,
                             ap_w, ap_b, bh_w, bh_b, out);
}

// round 11
// speedup vs baseline: 1.1008x; 1.1008x over previous
#include <cuda_runtime.h>
#include <cuda_bf16.h>
#include <cstdint>
#include <math.h>

#define An 32
#define Bn 128
#define Nn 4096
#define Tt 5
#define Hh 4
#define DHh 64
#define Dd 256
#define Ll 64
#define FIN1 24
#define NROWS 20480          // 640 blocks * 32 rows

typedef unsigned long long ull;

// ---------------- scratch ----------------
__device__ unsigned short g_x2h[NROWS * Dd];    // bf16 hi of x2 (row-major)
__device__ unsigned short g_x2l[NROWS * Dd];    // bf16 lo (residual)
__device__ unsigned short g_w2th[Dd * Dd];      // W2^T hi  [n][k]
__device__ unsigned short g_w2tl[Dd * Dd];      // W2^T lo
__device__ float g_ego[Tt * Bn * Dd];
__device__ float g_k[Tt * Bn * Dd];
__device__ float g_v[Tt * Bn * Dd];
__device__ float g_q[Bn * Dd];

// ---------------- f32x2 helpers ----------------
__device__ __forceinline__ ull pack2(float lo, float hi) {
    ull r; asm("mov.b64 %0, {%1, %2};" : "=l"(r) : "f"(lo), "f"(hi)); return r;
}
__device__ __forceinline__ ull dup2(float v) { return pack2(v, v); }
__device__ __forceinline__ void fma2(ull& acc, ull a, ull b) {
    asm("fma.rn.f32x2 %0, %1, %2, %0;" : "+l"(acc) : "l"(a), "l"(b));
}
__device__ __forceinline__ float2 unpack2(ull v) {
    float2 f; asm("mov.b64 {%0, %1}, %2;" : "=f"(f.x), "=f"(f.y) : "l"(v)); return f;
}

// ---------------- warp mma helper ----------------
__device__ __forceinline__ void mma16816(float* d,
    uint32_t a0, uint32_t a1, uint32_t a2, uint32_t a3,
    uint32_t b0, uint32_t b1)
{
    asm volatile("mma.sync.aligned.m16n8k16.row.col.f32.bf16.bf16.f32 "
        "{%0,%1,%2,%3}, {%4,%5,%6,%7}, {%8,%9}, {%0,%1,%2,%3};"
        : "+f"(d[0]), "+f"(d[1]), "+f"(d[2]), "+f"(d[3])
        : "r"(a0), "r"(a1), "r"(a2), "r"(a3), "r"(b0), "r"(b1));
}

// ---------------------------------------------------------------------------
// GAT layer 1 per (t, block): GEMM1 + logits + softmax + agg -> x2 (bf16 hi/lo)
// ---------------------------------------------------------------------------
#define G1_H 6912
#define G1_ALS 15232
#define G1_ALD 15360
#define G1_TOT 15488
#define HSTRIDE 260

__global__ __launch_bounds__(256, 3)
void gat1_kernel(const float* __restrict__ node_feats,
                 const float* __restrict__ W1,
                 const float* __restrict__ a1s, const float* __restrict__ a1d,
                 const float* __restrict__ b1)
{
    extern __shared__ float sm[];
    float* x1_sm  = sm;
    float* W1_sm  = sm + 32 * FIN1;
    float* alpha1 = sm;                 // alias (x1/W1 dead)
    float* h_sm   = sm + G1_H;
    float* als    = sm + G1_ALS;
    float* ald    = sm + G1_ALD;

    const int tid = threadIdx.x;
    const int t   = blockIdx.x / Bn;
    const int bb  = blockIdx.x % Bn;

    {
        const float* xblk = node_feats + ((size_t)t * Nn + (size_t)bb * An) * FIN1;
        for (int i = tid; i < 32 * FIN1; i += 256) x1_sm[i] = xblk[i];
        const float4* Wsrc = reinterpret_cast<const float4*>(W1);
        float4* Wdst = reinterpret_cast<float4*>(W1_sm);
        #pragma unroll
        for (int i = 0; i < (FIN1 * Dd) / 4; i += 256) Wdst[i + tid] = Wsrc[i + tid];
    }
    __syncthreads();

    const int cp = tid & 63;
    const int r0 = (tid >> 6) * 8;

    // GEMM1 (R5-proven 8x2 tiling)
    {
        ull acc0[8], acc1[8];
        #pragma unroll
        for (int i = 0; i < 8; i++) { acc0[i] = 0ull; acc1[i] = 0ull; }
        #pragma unroll
        for (int k = 0; k < FIN1; k += 2) {
            float2 xv[8];
            #pragma unroll
            for (int i = 0; i < 8; i++)
                xv[i] = *reinterpret_cast<const float2*>(&x1_sm[(r0 + i) * FIN1 + k]);
            {
                const ull* Wr = reinterpret_cast<const ull*>(&W1_sm[k * Dd]);
                ull w0 = Wr[cp], w1 = Wr[cp + 64];
                #pragma unroll
                for (int i = 0; i < 8; i++) { ull d = dup2(xv[i].x); fma2(acc0[i], d, w0); fma2(acc1[i], d, w1); }
            }
            {
                const ull* Wr = reinterpret_cast<const ull*>(&W1_sm[(k + 1) * Dd]);
                ull w0 = Wr[cp], w1 = Wr[cp + 64];
                #pragma unroll
                for (int i = 0; i < 8; i++) { ull d = dup2(xv[i].y); fma2(acc0[i], d, w0); fma2(acc1[i], d, w1); }
            }
        }
        ull* h64 = reinterpret_cast<ull*>(h_sm);
        #pragma unroll
        for (int i = 0; i < 8; i++) {
            h64[(r0 + i) * (HSTRIDE / 2) + cp]      = acc0[i];
            h64[(r0 + i) * (HSTRIDE / 2) + cp + 64] = acc1[i];
        }
    }
    __syncthreads();

    // logits1
    if (tid < 128) {
        const int r = tid & 31, head = tid >> 5;
        const float* hrow = &h_sm[r * HSTRIDE + head * DHh];
        const float* as = &a1s[head * DHh];
        const float* ad = &a1d[head * DHh];
        float s1 = 0.f, s2 = 0.f;
        #pragma unroll 8
        for (int j = 0; j < DHh; j++) { float hv = hrow[j]; s1 = fmaf(hv, as[j], s1); s2 = fmaf(hv, ad[j], s2); }
        als[head * 32 + r] = s1;
        ald[head * 32 + r] = s2;
    }
    __syncthreads();

    // softmax1
    if (tid < 128) {
        const int d = tid & 31, head = tid >> 5;
        float* arow = &alpha1[head * (32 * 33) + d * 33];
        const float adv = ald[head * 32 + d];
        float m = -1e30f;
        #pragma unroll
        for (int s = 0; s < 32; s++) {
            float e = als[head * 32 + s] + adv;
            e = (e >= 0.f) ? e : 0.2f * e;
            arow[s] = e; m = fmaxf(m, e);
        }
        float z = 0.f;
        #pragma unroll
        for (int s = 0; s < 32; s++) { float p = expf(arow[s] - m); arow[s] = p; z += p; }
        const float inv = 1.f / (z + 1e-16f);
        #pragma unroll
        for (int s = 0; s < 32; s++) arow[s] *= inv;
    }
    __syncthreads();

    // aggregation1 -> global bf16 hi/lo
    {
        const int head = tid >> 6;
        const int lane = tid & 63;
        const int cpl  = lane & 15;
        const int d0   = (lane >> 4) * 8;
        const ull* h64 = reinterpret_cast<const ull*>(h_sm);
        const float* arow = &alpha1[head * (32 * 33)];

        ull acc0[8], acc1[8];
        #pragma unroll
        for (int i = 0; i < 8; i++) { acc0[i] = 0ull; acc1[i] = 0ull; }
        #pragma unroll 4
        for (int s = 0; s < 32; s++) {
            ull hv0 = h64[s * (HSTRIDE / 2) + head * 32 + cpl];
            ull hv1 = h64[s * (HSTRIDE / 2) + head * 32 + cpl + 16];
            #pragma unroll
            for (int dd = 0; dd < 8; dd++) {
                ull a = dup2(arow[(d0 + dd) * 33 + s]);
                fma2(acc0[dd], a, hv0); fma2(acc1[dd], a, hv1);
            }
        }
        const int c0 = head * 64 + 2 * cpl;
        const int c1 = c0 + 32;
        float2 bv0 = *reinterpret_cast<const float2*>(&b1[c0]);
        float2 bv1 = *reinterpret_cast<const float2*>(&b1[c1]);
        #pragma unroll
        for (int dd = 0; dd < 8; dd++) {
            float2 o0 = unpack2(acc0[dd]);
            float2 o1 = unpack2(acc1[dd]);
            o0.x = fmaxf(o0.x + bv0.x, 0.f); o0.y = fmaxf(o0.y + bv0.y, 0.f);
            o1.x = fmaxf(o1.x + bv1.x, 0.f); o1.y = fmaxf(o1.y + bv1.y, 0.f);
            const size_t grow = (size_t)blockIdx.x * 32 + d0 + dd;
            {
                __nv_bfloat162 hv = __floats2bfloat162_rn(o0.x, o0.y);
                __nv_bfloat162 lv = __floats2bfloat162_rn(o0.x - __low2float(hv), o0.y - __high2float(hv));
                *reinterpret_cast<__nv_bfloat162*>(&g_x2h[grow * Dd + c0]) = hv;
                *reinterpret_cast<__nv_bfloat162*>(&g_x2l[grow * Dd + c0]) = lv;
            }
            {
                __nv_bfloat162 hv = __floats2bfloat162_rn(o1.x, o1.y);
                __nv_bfloat162 lv = __floats2bfloat162_rn(o1.x - __low2float(hv), o1.y - __high2float(hv));
                *reinterpret_cast<__nv_bfloat162*>(&g_x2h[grow * Dd + c1]) = hv;
                *reinterpret_cast<__nv_bfloat162*>(&g_x2l[grow * Dd + c1]) = lv;
            }
        }
    }
}

// ---------------------------------------------------------------------------
// W2 transpose + bf16 hi/lo split. grid 256 (n), 256 threads (k).
// ---------------------------------------------------------------------------
__global__ __launch_bounds__(256)
void prep_w2_kernel(const float* __restrict__ W2)
{
    const int n = blockIdx.x;
    const int k = threadIdx.x;
    float w = W2[(size_t)k * Dd + n];
    __nv_bfloat16 h = __float2bfloat16(w);
    __nv_bfloat16 l = __float2bfloat16(w - __bfloat162float(h));
    reinterpret_cast<__nv_bfloat16*>(g_w2th)[(size_t)n * Dd + k] = h;
    reinterpret_cast<__nv_bfloat16*>(g_w2tl)[(size_t)n * Dd + k] = l;
}

// ---------------------------------------------------------------------------
// GEMM2 (mma.sync, 3xBF16) with PER-HEAD fused GAT-2 tail.
// 320 CTAs x 256 threads, tile 128 rows x 128 cols (= 2 heads, 4 graph blocks).
// Epilogue reuses staging smem: tile[128][132] f32 + als/ald + alpha.
// smem = 73728 B -> 2 CTAs/SM preserved.
// ---------------------------------------------------------------------------
#define GP 72
#define TS2 132
#define EP_ALS (128 * TS2 * 4)          // 67584
#define EP_ALD (EP_ALS + 1024)
#define EP_ALPHA (EP_ALD + 1024)
#define G2_SMEM (4 * 128 * GP * 2)      // 73728

__global__ __launch_bounds__(256, 2)
void gemm2_fused_kernel(const float* __restrict__ a2s, const float* __restrict__ a2d,
                        const float* __restrict__ b2)
{
    extern __shared__ char smraw[];
    unsigned short* sAh = reinterpret_cast<unsigned short*>(smraw);
    unsigned short* sAl = sAh + 128 * GP;
    unsigned short* sBh = sAh + 2 * 128 * GP;
    unsigned short* sBl = sBh + 128 * GP;
    float* tile  = reinterpret_cast<float*>(smraw);
    float* als   = reinterpret_cast<float*>(smraw + EP_ALS);    // [2][128]
    float* ald   = reinterpret_cast<float*>(smraw + EP_ALD);
    float* alpha = reinterpret_cast<float*>(smraw + EP_ALPHA);  // [8][33]

    const int tid  = threadIdx.x;
    const int wid  = tid >> 5;
    const int lane = tid & 31;
    const int row0 = (blockIdx.x >> 1) * 128;
    const int n0   = (blockIdx.x & 1) * 128;
    const int g    = lane >> 2;          // 0..7
    const int cq   = (lane & 3) * 2;     // 0,2,4,6

    float acc[16][4];
    #pragma unroll
    for (int j = 0; j < 16; j++)
        #pragma unroll
        for (int i = 0; i < 4; i++) acc[j][i] = 0.f;

    for (int kc = 0; kc < Dd; kc += 64) {
        __syncthreads();
        #pragma unroll
        for (int q = tid; q < 2048; q += 256) {
            int r  = q >> 4;
            int k4 = (q & 15) * 4;
            size_t ga = (size_t)(row0 + r) * Dd + kc + k4;
            size_t gb = (size_t)(n0 + r) * Dd + kc + k4;
            *reinterpret_cast<ull*>(&sAh[r * GP + k4]) = *reinterpret_cast<const ull*>(&g_x2h[ga]);
            *reinterpret_cast<ull*>(&sAl[r * GP + k4]) = *reinterpret_cast<const ull*>(&g_x2l[ga]);
            *reinterpret_cast<ull*>(&sBh[r * GP + k4]) = *reinterpret_cast<const ull*>(&g_w2th[gb]);
            *reinterpret_cast<ull*>(&sBl[r * GP + k4]) = *reinterpret_cast<const ull*>(&g_w2tl[gb]);
        }
        __syncthreads();

        #pragma unroll
        for (int s = 0; s < 4; s++) {
            const int kb = s * 16 + cq;
            const int ra = wid * 16 + g;
            uint32_t ah0 = *reinterpret_cast<const uint32_t*>(&sAh[ra * GP + kb]);
            uint32_t ah1 = *reinterpret_cast<const uint32_t*>(&sAh[(ra + 8) * GP + kb]);
            uint32_t ah2 = *reinterpret_cast<const uint32_t*>(&sAh[ra * GP + kb + 8]);
            uint32_t ah3 = *reinterpret_cast<const uint32_t*>(&sAh[(ra + 8) * GP + kb + 8]);
            uint32_t al0 = *reinterpret_cast<const uint32_t*>(&sAl[ra * GP + kb]);
            uint32_t al1 = *reinterpret_cast<const uint32_t*>(&sAl[(ra + 8) * GP + kb]);
            uint32_t al2 = *reinterpret_cast<const uint32_t*>(&sAl[ra * GP + kb + 8]);
            uint32_t al3 = *reinterpret_cast<const uint32_t*>(&sAl[(ra + 8) * GP + kb + 8]);

            #pragma unroll
            for (int j = 0; j < 16; j++) {
                const int nb = j * 8 + g;
                uint32_t bh0 = *reinterpret_cast<const uint32_t*>(&sBh[nb * GP + kb]);
                uint32_t bh1 = *reinterpret_cast<const uint32_t*>(&sBh[nb * GP + kb + 8]);
                uint32_t bl0 = *reinterpret_cast<const uint32_t*>(&sBl[nb * GP + kb]);
                uint32_t bl1 = *reinterpret_cast<const uint32_t*>(&sBl[nb * GP + kb + 8]);
                mma16816(acc[j], ah0, ah1, ah2, ah3, bh0, bh1);   // hi*hi
                mma16816(acc[j], ah0, ah1, ah2, ah3, bl0, bl1);   // hi*lo
                mma16816(acc[j], al0, al1, al2, al3, bh0, bh1);   // lo*hi
            }
        }
    }
    __syncthreads();   // staging dead; reuse smem as epilogue tile

    // accumulators -> smem tile (local cols 0..127)
    {
        const int row = wid * 16 + g;
        #pragma unroll
        for (int j = 0; j < 16; j++) {
            const int col = j * 8 + cq;
            *reinterpret_cast<float2*>(&tile[row * TS2 + col])       = make_float2(acc[j][0], acc[j][1]);
            *reinterpret_cast<float2*>(&tile[(row + 8) * TS2 + col]) = make_float2(acc[j][2], acc[j][3]);
        }
    }
    __syncthreads();

    // logits2 for the CTA's 2 heads: 256 threads = (head_local 0..1) x (row 0..127)
    {
        const int hl = tid >> 7;
        const int r = tid & 127;
        const int ghead = (n0 >> 6) + hl;
        const float* hrow = &tile[r * TS2 + hl * DHh];
        const float* as = &a2s[ghead * DHh];
        const float* ad = &a2d[ghead * DHh];
        float s1 = 0.f, s2 = 0.f;
        #pragma unroll 8
        for (int j = 0; j < DHh; j++) { float hv = hrow[j]; s1 = fmaf(hv, as[j], s1); s2 = fmaf(hv, ad[j], s2); }
        als[hl * 128 + r] = s1;
        ald[hl * 128 + r] = s2;
    }
    __syncthreads();

    // softmax2 (d=0) per (block 0..3, head_local 0..1)
    if (tid < 8) {
        const int blk = tid >> 1;
        const int hl = tid & 1;
        const float adv = ald[hl * 128 + blk * 32];
        const float* asrc = &als[hl * 128 + blk * 32];
        float* arow = &alpha[(blk * 2 + hl) * 33];
        float m = -1e30f;
        #pragma unroll
        for (int s = 0; s < 32; s++) {
            float e = asrc[s] + adv;
            e = (e >= 0.f) ? e : 0.2f * e;
            arow[s] = e; m = fmaxf(m, e);
        }
        float z = 0.f;
        #pragma unroll
        for (int s = 0; s < 32; s++) { float p = expf(arow[s] - m); arow[s] = p; z += p; }
        const float inv = 1.f / (z + 1e-16f);
        #pragma unroll
        for (int s = 0; s < 32; s++) arow[s] *= inv;
    }
    __syncthreads();

    // aggregation2 (d=0): 4 blocks x 128 local cols = 512 outputs, 2 per thread
    #pragma unroll
    for (int it = tid; it < 512; it += 256) {
        const int blk = it >> 7;
        const int c = it & 127;
        const int hl = c >> 6;
        const float* arow = &alpha[(blk * 2 + hl) * 33];
        const float* hcol = &tile[blk * 32 * TS2 + c];
        float a = 0.f;
        #pragma unroll 8
        for (int s = 0; s < 32; s++)
            a = fmaf(arow[s], hcol[s * TS2], a);
        a = fmaxf(a + b2[n0 + c], 0.f);
        g_ego[(size_t)((blockIdx.x >> 1) * 4 + blk) * Dd + n0 + c] = a;
    }
}

// ---------------------------------------------------------------------------
// QKV GEMM, smem-staged weights. 352 CTAs: tile=(id>>2) 16 rows, ch=(id&3)
// 64-col quarter. tiles 0..39 K, 40..79 V, 80..87 Q(t=4).
// ---------------------------------------------------------------------------
__global__ __launch_bounds__(256)
void qkv_kernel(const float* __restrict__ wq, const float* __restrict__ bq,
                const float* __restrict__ wk, const float* __restrict__ bk,
                const float* __restrict__ wv, const float* __restrict__ bv)
{
    __shared__ float x_sm[16 * Dd];
    __shared__ float w_sm[64 * 64];

    const int id   = blockIdx.x;
    const int tile = id >> 2;
    const int ch   = id & 3;
    const int tid  = threadIdx.x;

    const float* W; const float* bias; float* outbase; int row0; int xrow0;
    if (tile < 40)      { W = wk; bias = bk; row0 = tile * 16;        outbase = g_k; xrow0 = row0; }
    else if (tile < 80) { W = wv; bias = bv; row0 = (tile - 40) * 16; outbase = g_v; xrow0 = row0; }
    else                { W = wq; bias = bq; row0 = (tile - 80) * 16; outbase = g_q; xrow0 = 512 + row0; }

    {
        const float4* s4 = reinterpret_cast<const float4*>(g_ego + (size_t)xrow0 * Dd);
        float4* d4 = reinterpret_cast<float4*>(x_sm);
        #pragma unroll
        for (int i = 0; i < (16 * Dd) / 4; i += 256) d4[i + tid] = s4[i + tid];
    }

    const int cp = tid & 31;          // col pair within 64-col quarter
    const int r0 = (tid >> 5) * 2;    // 2 rows per thread

    ull acc[2];
    acc[0] = 0ull; acc[1] = 0ull;

    #pragma unroll 1
    for (int c4 = 0; c4 < 4; c4++) {
        __syncthreads();
        // stage W rows [c4*64, +64), cols [ch*64, +64): 1024 float4, 4/thread
        {
            float4* wd = reinterpret_cast<float4*>(w_sm);
            #pragma unroll
            for (int i = tid; i < 1024; i += 256) {
                int r   = i >> 4;          // 16 float4 per row
                int c4i = i & 15;
                wd[i] = *reinterpret_cast<const float4*>(&W[(size_t)(c4 * 64 + r) * Dd + ch * 64 + c4i * 4]);
            }
        }
        __syncthreads();

        const ull* wu = reinterpret_cast<const ull*>(w_sm);   // [64][32 ull]
        #pragma unroll 4
        for (int k = 0; k < 64; k += 2) {
            float2 xv0 = *reinterpret_cast<const float2*>(&x_sm[r0 * Dd + c4 * 64 + k]);
            float2 xv1 = *reinterpret_cast<const float2*>(&x_sm[(r0 + 1) * Dd + c4 * 64 + k]);
            ull w0 = wu[k * 32 + cp];
            ull w1 = wu[(k + 1) * 32 + cp];
            { ull d = dup2(xv0.x); fma2(acc[0], d, w0); }
            { ull d = dup2(xv1.x); fma2(acc[1], d, w0); }
            { ull d = dup2(xv0.y); fma2(acc[0], d, w1); }
            { ull d = dup2(xv1.y); fma2(acc[1], d, w1); }
        }
    }

    const int c = ch * 64 + 2 * cp;
    float2 bv2 = *reinterpret_cast<const float2*>(&bias[c]);
    #pragma unroll
    for (int r = 0; r < 2; r++) {
        float2 o = unpack2(acc[r]);
        o.x += bv2.x; o.y += bv2.y;
        *reinterpret_cast<float2*>(&outbase[(size_t)(row0 + r0 + r) * Dd + c]) = o;
    }
}

// ---------------------------------------------------------------------------
// attn + wo + output heads, fused. 16-wide batched weight loads (proven).
// ---------------------------------------------------------------------------
__global__ __launch_bounds__(256)
void post_kernel(const float* __restrict__ wo, const float* __restrict__ bo,
                 const float* __restrict__ lm_w, const float* __restrict__ lm_b,
                 const float* __restrict__ lv_w, const float* __restrict__ lv_b,
                 const float* __restrict__ ap_w, const float* __restrict__ ap_b,
                 const float* __restrict__ bh_w, const float* __restrict__ bh_b,
                 float* __restrict__ out)
{
    __shared__ float ksm[Tt][Dd];
    __shared__ float vsm[Tt][Dd];
    __shared__ float qsm[Dd];
    __shared__ float attn[Hh][Tt];
    __shared__ float ctx[Dd];
    __shared__ float feat[Dd];
    __shared__ float musm[Ll];

    const int b = blockIdx.x;
    const int tid = threadIdx.x;
    const int c = tid;

    #pragma unroll
    for (int t = 0; t < Tt; t++) {
        ksm[t][c] = g_k[((size_t)t * Bn + b) * Dd + c];
        vsm[t][c] = g_v[((size_t)t * Bn + b) * Dd + c];
    }
    qsm[c] = g_q[(size_t)b * Dd + c];
    __syncthreads();

    if (tid < Hh * Tt) {
        const int head = tid / Tt;
        const int t = tid % Tt;
        float s = 0.f;
        #pragma unroll 8
        for (int j = 0; j < DHh; j++)
            s = fmaf(qsm[head * DHh + j], ksm[t][head * DHh + j], s);
        attn[head][t] = s * 0.125f;
    }
    __syncthreads();

    if (tid < Hh) {
        float m = -1e30f;
        #pragma unroll
        for (int t = 0; t < Tt; t++) m = fmaxf(m, attn[tid][t]);
        float z = 0.f;
        #pragma unroll
        for (int t = 0; t < Tt; t++) { float p = expf(attn[tid][t] - m); attn[tid][t] = p; z += p; }
        float inv = 1.f / z;
        #pragma unroll
        for (int t = 0; t < Tt; t++) attn[tid][t] *= inv;
    }
    __syncthreads();

    {
        const int head = c >> 6;
        float a = 0.f;
        #pragma unroll
        for (int t = 0; t < Tt; t++) a = fmaf(attn[head][t], vsm[t][c], a);
        ctx[c] = a;
    }
    __syncthreads();

    {
        float f = bo[c];
        #pragma unroll 1
        for (int k = 0; k < Dd; k += 16) {
            float w[16];
            #pragma unroll
            for (int j = 0; j < 16; j++) w[j] = __ldg(&wo[(size_t)(k + j) * Dd + c]);
            #pragma unroll
            for (int j = 0; j < 16; j++) f = fmaf(ctx[k + j], w[j], f);
        }
        feat[c] = f;
    }
    __syncthreads();

    float* ob = out + (size_t)b * 400;

    if (tid < 64) {
        float m = lm_b[tid];
        #pragma unroll 1
        for (int k = 0; k < Dd; k += 16) {
            float w[16];
            #pragma unroll
            for (int j = 0; j < 16; j++) w[j] = __ldg(&lm_w[(size_t)(k + j) * Ll + tid]);
            #pragma unroll
            for (int j = 0; j < 16; j++) m = fmaf(feat[k + j], w[j], m);
        }
        musm[tid] = m;
        ob[tid] = m;
    } else if (tid < 128) {
        const int cc = tid - 64;
        float m = lv_b[cc];
        #pragma unroll 1
        for (int k = 0; k < Dd; k += 16) {
            float w[16];
            #pragma unroll
            for (int j = 0; j < 16; j++) w[j] = __ldg(&lv_w[(size_t)(k + j) * Ll + cc]);
            #pragma unroll
            for (int j = 0; j < 16; j++) m = fmaf(feat[k + j], w[j], m);
        }
        ob[64 + cc] = m;
    } else if (tid < 144) {
        const int cc = tid - 128;
        float m = bh_b[cc];
        #pragma unroll 1
        for (int k = 0; k < Dd; k += 16) {
            float w[16];
            #pragma unroll
            for (int j = 0; j < 16; j++) w[j] = __ldg(&bh_w[(size_t)(k + j) * 16 + cc]);
            #pragma unroll
            for (int j = 0; j < 16; j++) m = fmaf(feat[k + j], w[j], m);
        }
        ob[384 + cc] = m;
    }
    __syncthreads();

    {
        float a = ap_b[c];
        #pragma unroll 1
        for (int k = 0; k < Ll; k += 16) {
            float w[16];
            #pragma unroll
            for (int j = 0; j < 16; j++) w[j] = __ldg(&ap_w[(size_t)(k + j) * Dd + c]);
            #pragma unroll
            for (int j = 0; j < 16; j++) a = fmaf(musm[k + j], w[j], a);
        }
        ob[128 + c] = a;
    }
}

// ---------------------------------------------------------------------------
extern "C" void kernel_launch(void* const* d_in, const int* in_sizes, int n_in,
                              void* d_out, int out_size)
{
    const float* node_feats = (const float*)d_in[0];
    const float* gat1_w  = (const float*)d_in[2];
    const float* gat1_as = (const float*)d_in[3];
    const float* gat1_ad = (const float*)d_in[4];
    const float* gat1_b  = (const float*)d_in[5];
    const float* gat2_w  = (const float*)d_in[6];
    const float* gat2_as = (const float*)d_in[7];
    const float* gat2_ad = (const float*)d_in[8];
    const float* gat2_b  = (const float*)d_in[9];
    const float* wq = (const float*)d_in[10];
    const float* bq = (const float*)d_in[11];
    const float* wk = (const float*)d_in[12];
    const float* bk = (const float*)d_in[13];
    const float* wv = (const float*)d_in[14];
    const float* bv = (const float*)d_in[15];
    const float* wo = (const float*)d_in[16];
    const float* bo = (const float*)d_in[17];
    const float* lm_w = (const float*)d_in[18];
    const float* lm_b = (const float*)d_in[19];
    const float* lv_w = (const float*)d_in[20];
    const float* lv_b = (const float*)d_in[21];
    const float* ap_w = (const float*)d_in[22];
    const float* ap_b = (const float*)d_in[23];
    const float* bh_w = (const float*)d_in[24];
    const float* bh_b = (const float*)d_in[25];
    float* out = (float*)d_out;

    const size_t sm1 = (size_t)G1_TOT * sizeof(float);
    cudaFuncSetAttribute(gat1_kernel, cudaFuncAttributeMaxDynamicSharedMemorySize, (int)sm1);
    cudaFuncSetAttribute(gemm2_fused_kernel, cudaFuncAttributeMaxDynamicSharedMemorySize, G2_SMEM);

    prep_w2_kernel<<<256, 256>>>(gat2_w);
    gat1_kernel<<<Tt * Bn, 256, sm1>>>(node_feats, gat1_w, gat1_as, gat1_ad, gat1_b);
    gemm2_fused_kernel<<<(NROWS / 128) * 2, 256, G2_SMEM>>>(gat2_as, gat2_ad, gat2_b);
    qkv_kernel<<<352, 256>>>(wq, bq, wk, bk, wv, bv);
    post_kernel<<<Bn, 256>>>(wo, bo, lm_w, lm_b, lv_w, lv_b,
                             ap_w, ap_b, bh_w, bh_b, out);
}